// round 14
// baseline (speedup 1.0000x reference)
#include <cuda_runtime.h>
#include <cuda_bf16.h>
#include <math.h>

#define VOCAB 50000
#define EDIM  256
#define HDIM  512
#define BB    32
#define SS    512
#define TWOH  1024
#define XDIM  1280   // E + 2H
#define G3H   1536   // 3H
#define WST   20     // smem row stride in 32-bit words (bf16 kernels)
#define PAD   36     // smem row stride in floats (tf32 kernel)
#define NSPL  8      // vocab splits for softmax stats

// ---------------- device scratch ----------------
__device__ float g_x[BB * XDIM];
__device__ float g_gi[BB * G3H];
__device__ float g_gh[BB * G3H];
__device__ float g_state[BB * HDIM];
__device__ float g_score_g[BB * VOCAB];
__device__ float g_score_c[BB * SS];
__device__ float g_pm[BB * NSPL];
__device__ float g_pz[BB * NSPL];
__device__ float g_mx[BB];
__device__ float g_invZ[BB];
__device__ __align__(16) unsigned g_enc_bf16[BB * SS * (TWOH / 2)];  // encoded, packed bf16
__device__ __align__(16) unsigned g_wc_bf16[HDIM * (TWOH / 2)];      // Wc_w, packed bf16

__device__ __forceinline__ void mma_bf16(float* d, const unsigned* a, const unsigned* b) {
    asm volatile(
        "mma.sync.aligned.m16n8k16.row.col.f32.bf16.bf16.f32 "
        "{%0,%1,%2,%3}, {%4,%5,%6,%7}, {%8,%9}, {%0,%1,%2,%3};\n"
        : "+f"(d[0]), "+f"(d[1]), "+f"(d[2]), "+f"(d[3])
        : "r"(a[0]), "r"(a[1]), "r"(a[2]), "r"(a[3]), "r"(b[0]), "r"(b[1]));
}

__device__ __forceinline__ void mma_tf32(float* d, const unsigned* a, const unsigned* b) {
    asm volatile(
        "mma.sync.aligned.m16n8k8.row.col.f32.tf32.tf32.f32 "
        "{%0,%1,%2,%3}, {%4,%5,%6,%7}, {%8,%9}, {%0,%1,%2,%3};\n"
        : "+f"(d[0]), "+f"(d[1]), "+f"(d[2]), "+f"(d[3])
        : "r"(a[0]), "r"(a[1]), "r"(a[2]), "r"(a[3]), "r"(b[0]), "r"(b[1]));
}

__device__ __forceinline__ void ldsm_x4(unsigned& r0, unsigned& r1, unsigned& r2,
                                        unsigned& r3, unsigned addr) {
    asm volatile("ldmatrix.sync.aligned.m8n8.x4.shared.b16 {%0,%1,%2,%3}, [%4];"
        : "=r"(r0), "=r"(r1), "=r"(r2), "=r"(r3) : "r"(addr));
}

__device__ __forceinline__ void cvt_pair(float x0, float x1, unsigned& hi, unsigned& lo) {
    __nv_bfloat162 h = __floats2bfloat162_rn(x0, x1);
    float r0 = x0 - __bfloat162float(h.x);
    float r1 = x1 - __bfloat162float(h.y);
    __nv_bfloat162 l = __floats2bfloat162_rn(r0, r1);
    hi = *(unsigned*)&h;
    lo = *(unsigned*)&l;
}

__device__ __forceinline__ unsigned pack_hi(float x0, float x1) {
    __nv_bfloat162 h = __floats2bfloat162_rn(x0, x1);
    return *(unsigned*)&h;
}

__device__ __forceinline__ float sigf(float x) { return 1.f / (1.f + expf(-x)); }

// ---------------- bf16 pre-convert (runs on side stream) ----------------
__global__ void k_cvt(const float* __restrict__ enc, const float* __restrict__ wc) {
    long long t = (long long)blockIdx.x * 256 + threadIdx.x;   // one uint4 (8 floats) per thread
    const long long NA = (long long)BB * SS * TWOH / 8;        // 2,097,152
    const long long NW = (long long)HDIM * TWOH / 8;           // 65,536
    if (t < NA) {
        const float4* src = (const float4*)enc;
        float4 a = src[2 * t], b = src[2 * t + 1];
        ((uint4*)g_enc_bf16)[t] = make_uint4(pack_hi(a.x, a.y), pack_hi(a.z, a.w),
                                             pack_hi(b.x, b.y), pack_hi(b.z, b.w));
    } else if (t < NA + NW) {
        long long i = t - NA;
        const float4* src = (const float4*)wc;
        float4 a = src[2 * i], b = src[2 * i + 1];
        ((uint4*)g_wc_bf16)[i] = make_uint4(pack_hi(a.x, a.y), pack_hi(a.z, a.w),
                                            pack_hi(b.x, b.y), pack_hi(b.z, b.w));
    }
}

// ---------------- setup: bias seeding + score_c zero + build x ----------------
__global__ void k_setup(const float* __restrict__ bih, const float* __restrict__ bhh,
                        const int* __restrict__ input_idx,
                        const float* __restrict__ embed_w,
                        const float* __restrict__ weighted) {
    int t = blockIdx.x * 256 + threadIdx.x;
    if (t < BB * G3H) { int n = t % G3H; g_gi[t] = bih[n]; g_gh[t] = bhh[n]; }
    if (t < BB * SS) g_score_c[t] = 0.f;
    if (t < BB * XDIM) {
        int b = t / XDIM, i = t % XDIM;
        g_x[t] = (i < EDIM) ? embed_w[(size_t)input_idx[b] * EDIM + i]
                            : weighted[b * TWOH + (i - EDIM)];
    }
}

// =====================================================================
// Fused GRU GEMMs: blocks [0,192): gi += x @ wih^T; [192,288): gh += prev @ whh^T
// bf16x2 3-pass (full precision), 128 threads, 64 n-rows/tile, N=G3H both.
// =====================================================================
__global__ __launch_bounds__(128) void k_gigh(
        const float* __restrict__ x, const float* __restrict__ prev,
        const float* __restrict__ wih, const float* __restrict__ whh) {
    __shared__ unsigned Wh[64 * WST], Wl[64 * WST], Xh[32 * WST], Xl[32 * WST];
    int bid = blockIdx.x;
    const float *A, *W; float* C; int K, tile, kbeg;
    if (bid < 192) {
        A = x; W = wih; C = g_gi; K = XDIM;
        tile = bid % 24; kbeg = (bid / 24) * 160;
    } else {
        int l = bid - 192;
        A = prev; W = whh; C = g_gh; K = HDIM;
        tile = l % 24; kbeg = (l / 24) * 128;
    }
    int kend = kbeg + ((bid < 192) ? 160 : 128);
    int n0 = tile * 64;
    int tid = threadIdx.x, warp = tid >> 5, lane = tid & 31;
    int gid = lane >> 2, t = lane & 3;
    float acc[4][4] = {};

    int wrow = tid >> 1;
    int wc0 = (tid & 1) * 16, wcw = (tid & 1) * 8;
    int xrow = tid >> 2, xc0 = (tid & 3) * 8;

    for (int k0 = kbeg; k0 < kend; k0 += 32) {
        #pragma unroll
        for (int i = 0; i < 2; i++) {
            float4 v  = *(const float4*)(W + (size_t)(n0 + wrow) * K + k0 + wc0 + 8 * i);
            float4 v2 = *(const float4*)(W + (size_t)(n0 + wrow) * K + k0 + wc0 + 8 * i + 4);
            unsigned h0, l0, h1, l1, h2, l2, h3, l3;
            cvt_pair(v.x, v.y, h0, l0);  cvt_pair(v.z, v.w, h1, l1);
            cvt_pair(v2.x, v2.y, h2, l2); cvt_pair(v2.z, v2.w, h3, l3);
            Wh[wrow * WST + wcw + 4 * i]     = h0;
            Wh[wrow * WST + wcw + 4 * i + 1] = h1;
            Wh[wrow * WST + wcw + 4 * i + 2] = h2;
            Wh[wrow * WST + wcw + 4 * i + 3] = h3;
            Wl[wrow * WST + wcw + 4 * i]     = l0;
            Wl[wrow * WST + wcw + 4 * i + 1] = l1;
            Wl[wrow * WST + wcw + 4 * i + 2] = l2;
            Wl[wrow * WST + wcw + 4 * i + 3] = l3;
        }
        #pragma unroll
        for (int i = 0; i < 2; i++) {
            float4 v = *(const float4*)(A + (size_t)xrow * K + k0 + xc0 + 4 * i);
            unsigned h0, l0, h1, l1;
            cvt_pair(v.x, v.y, h0, l0); cvt_pair(v.z, v.w, h1, l1);
            Xh[xrow * WST + (xc0 >> 1) + 2 * i]     = h0;
            Xh[xrow * WST + (xc0 >> 1) + 2 * i + 1] = h1;
            Xl[xrow * WST + (xc0 >> 1) + 2 * i]     = l0;
            Xl[xrow * WST + (xc0 >> 1) + 2 * i + 1] = l1;
        }
        __syncthreads();
        #pragma unroll
        for (int s = 0; s < 2; s++) {
            int kb = s * 8;
            int rb = warp * 16;
            unsigned ah[4], al[4];
            ah[0] = Wh[(rb + gid) * WST + kb + t];     ah[1] = Wh[(rb + gid + 8) * WST + kb + t];
            ah[2] = Wh[(rb + gid) * WST + kb + t + 4]; ah[3] = Wh[(rb + gid + 8) * WST + kb + t + 4];
            al[0] = Wl[(rb + gid) * WST + kb + t];     al[1] = Wl[(rb + gid + 8) * WST + kb + t];
            al[2] = Wl[(rb + gid) * WST + kb + t + 4]; al[3] = Wl[(rb + gid + 8) * WST + kb + t + 4];
            #pragma unroll
            for (int bt = 0; bt < 4; bt++) {
                unsigned bh[2], bl[2];
                bh[0] = Xh[(bt * 8 + gid) * WST + kb + t];
                bh[1] = Xh[(bt * 8 + gid) * WST + kb + t + 4];
                bl[0] = Xl[(bt * 8 + gid) * WST + kb + t];
                bl[1] = Xl[(bt * 8 + gid) * WST + kb + t + 4];
                mma_bf16(acc[bt], ah, bh);
                mma_bf16(acc[bt], ah, bl);
                mma_bf16(acc[bt], al, bh);
            }
        }
        __syncthreads();
    }

    int nb = n0 + warp * 16 + gid;
    #pragma unroll
    for (int bt = 0; bt < 4; bt++) {
        int bc = bt * 8 + 2 * t;
        atomicAdd(&C[(size_t)bc * G3H + nb],           acc[bt][0]);
        atomicAdd(&C[(size_t)(bc + 1) * G3H + nb],     acc[bt][1]);
        atomicAdd(&C[(size_t)bc * G3H + nb + 8],       acc[bt][2]);
        atomicAdd(&C[(size_t)(bc + 1) * G3H + nb + 8], acc[bt][3]);
    }
}

// ---------------- GRU cell elementwise ----------------
__global__ void k_gru(const float* __restrict__ prev, float* __restrict__ out_state) {
    int b = blockIdx.x, j = threadIdx.x;
    float gir = g_gi[b * G3H + j];
    float giz = g_gi[b * G3H + HDIM + j];
    float gin = g_gi[b * G3H + 2 * HDIM + j];
    float ghr = g_gh[b * G3H + j];
    float ghz = g_gh[b * G3H + HDIM + j];
    float ghn = g_gh[b * G3H + 2 * HDIM + j];
    float r = sigf(gir + ghr);
    float z = sigf(giz + ghz);
    float n = tanhf(gin + r * ghn);
    float h = prev[b * HDIM + j];
    float st = (1.f - z) * n + z * h;
    g_state[b * HDIM + j] = st;
    out_state[b * HDIM + j] = st;
}

// =====================================================================
// Fused Wc GEMM: bf16 inputs pre-converted in global; ldmatrix; pipelined.
// =====================================================================
__global__ __launch_bounds__(256) void k_wc_mma(const float* __restrict__ bias) {
    __shared__ unsigned Ah[2][128 * WST], Bh[2][128 * WST];
    int tid = threadIdx.x;
    int warp = tid >> 5, lane = tid & 31;
    int gid = lane >> 2, t = lane & 3;
    int wm = warp >> 2, wn = warp & 3;
    int m0 = blockIdx.y * 128, n0 = blockIdx.x * 128;

    float acc[4][4][4] = {};

    int srow = tid >> 1;
    int half = tid & 1;
    int scw = half * 8;

    unsigned smem_a[2], smem_b[2];
    smem_a[0] = (unsigned)__cvta_generic_to_shared(Ah[0]);
    smem_a[1] = (unsigned)__cvta_generic_to_shared(Ah[1]);
    smem_b[0] = (unsigned)__cvta_generic_to_shared(Bh[0]);
    smem_b[1] = (unsigned)__cvta_generic_to_shared(Bh[1]);
    int lane15 = lane & 15;
    int asel   = lane >> 4;
    int li     = lane & 7;
    int bsel   = lane >> 3;

    const uint4* pa = (const uint4*)g_enc_bf16 + (size_t)(m0 + srow) * 128 + half * 2;
    const uint4* pw = (const uint4*)g_wc_bf16 + (size_t)(n0 + srow) * 128 + half * 2;

    uint4 va0, va1, vw0, vw1;
    va0 = pa[0]; va1 = pa[1]; vw0 = pw[0]; vw1 = pw[1];
    {
        unsigned* dsta = Ah[0] + srow * WST + scw;
        unsigned* dstb = Bh[0] + srow * WST + scw;
        *(uint4*)dsta = va0; *(uint4*)(dsta + 4) = va1;
        *(uint4*)dstb = vw0; *(uint4*)(dstb + 4) = vw1;
    }
    __syncthreads();

    const int NITER = TWOH / 32;   // 32
    for (int it = 0; it < NITER; it++) {
        int cur = it & 1;
        bool more = (it + 1) < NITER;
        if (more) {
            int o = (it + 1) * 4;
            va0 = pa[o]; va1 = pa[o + 1];
            vw0 = pw[o]; vw1 = pw[o + 1];
        }
        #pragma unroll
        for (int s = 0; s < 2; s++) {
            int kb = s * 8;
            unsigned ah[4][4], bh[4][2];
            #pragma unroll
            for (int mt = 0; mt < 4; mt++) {
                unsigned addr = smem_a[cur] +
                    (((wm * 64 + mt * 16 + lane15) * WST + kb + asel * 4) << 2);
                ldsm_x4(ah[mt][0], ah[mt][1], ah[mt][2], ah[mt][3], addr);
            }
            #pragma unroll
            for (int p = 0; p < 2; p++) {
                int row = wn * 32 + p * 16 + (bsel >> 1) * 8 + li;
                unsigned addr = smem_b[cur] + ((row * WST + kb + (bsel & 1) * 4) << 2);
                ldsm_x4(bh[2 * p][0], bh[2 * p][1], bh[2 * p + 1][0], bh[2 * p + 1][1], addr);
            }
            #pragma unroll
            for (int mt = 0; mt < 4; mt++)
                #pragma unroll
                for (int nt = 0; nt < 4; nt++)
                    mma_bf16(acc[mt][nt], ah[mt], bh[nt]);
        }
        if (more) {
            int nxt = cur ^ 1;
            unsigned* dsta = Ah[nxt] + srow * WST + scw;
            unsigned* dstb = Bh[nxt] + srow * WST + scw;
            *(uint4*)dsta = va0; *(uint4*)(dsta + 4) = va1;
            *(uint4*)dstb = vw0; *(uint4*)(dstb + 4) = vw1;
        }
        __syncthreads();
    }

    int b = m0 >> 9;
    #pragma unroll
    for (int mt = 0; mt < 4; mt++) {
        float r0 = 0.f, r1 = 0.f;
        #pragma unroll
        for (int nt = 0; nt < 4; nt++) {
            int nbase = n0 + wn * 32 + nt * 8 + t * 2;
            #pragma unroll
            for (int j = 0; j < 2; j++) {
                float bs = bias[nbase + j];
                float st = g_state[b * HDIM + nbase + j];
                r0 += sigf(acc[mt][nt][j] + bs) * st;
                r1 += sigf(acc[mt][nt][2 + j] + bs) * st;
            }
        }
        r0 += __shfl_xor_sync(0xffffffffu, r0, 1);
        r0 += __shfl_xor_sync(0xffffffffu, r0, 2);
        r1 += __shfl_xor_sync(0xffffffffu, r1, 1);
        r1 += __shfl_xor_sync(0xffffffffu, r1, 2);
        if (t == 0) {
            int row = m0 + wm * 64 + mt * 16 + gid;
            atomicAdd(&g_score_c[row], r0);
            atomicAdd(&g_score_c[row + 8], r1);
        }
    }
}

// =====================================================================
// Wo GEMM (tf32): C[32][N] = A[32][K] @ W[N][K]^T + bias
// =====================================================================
__global__ __launch_bounds__(256) void k_wo_tf32(
        const float* __restrict__ A, const float* __restrict__ W,
        const float* __restrict__ bias, float* __restrict__ C,
        int N, int K) {
    __shared__ float Ws[128 * PAD];
    __shared__ float Xs[32 * PAD];
    __shared__ float Cs[32 * 136];
    int tid = threadIdx.x;
    int warp = tid >> 5, lane = tid & 31;
    int gid = lane >> 2, t = lane & 3;
    int n0 = blockIdx.x * 128;

    float acc[4][4] = {};

    int wrow = tid >> 1, wcol = (tid & 1) * 16;
    int xb = tid >> 3, xk = (tid & 7) * 4;
    bool wok = (n0 + wrow) < N;

    for (int k0 = 0; k0 < K; k0 += 32) {
        #pragma unroll
        for (int i = 0; i < 4; i++) {
            float4 v = make_float4(0.f, 0.f, 0.f, 0.f);
            if (wok) v = *(const float4*)(W + (size_t)(n0 + wrow) * K + k0 + wcol + 4 * i);
            *(float4*)(Ws + wrow * PAD + wcol + 4 * i) = v;
        }
        {
            float4 v = *(const float4*)(A + (size_t)xb * K + k0 + xk);
            *(float4*)(Xs + xb * PAD + xk) = v;
        }
        __syncthreads();
        #pragma unroll
        for (int ks = 0; ks < 32; ks += 8) {
            unsigned a[4];
            int rb = warp * 16;
            a[0] = __float_as_uint(Ws[(rb + gid) * PAD + ks + t]);
            a[1] = __float_as_uint(Ws[(rb + gid + 8) * PAD + ks + t]);
            a[2] = __float_as_uint(Ws[(rb + gid) * PAD + ks + t + 4]);
            a[3] = __float_as_uint(Ws[(rb + gid + 8) * PAD + ks + t + 4]);
            #pragma unroll
            for (int bt = 0; bt < 4; bt++) {
                unsigned bb[2];
                bb[0] = __float_as_uint(Xs[(bt * 8 + gid) * PAD + ks + t]);
                bb[1] = __float_as_uint(Xs[(bt * 8 + gid) * PAD + ks + t + 4]);
                mma_tf32(acc[bt], a, bb);
            }
        }
        __syncthreads();
    }

    #pragma unroll
    for (int bt = 0; bt < 4; bt++) {
        int bc = bt * 8 + t * 2;
        int nl = warp * 16 + gid;
        Cs[bc * 136 + nl]           = acc[bt][0];
        Cs[(bc + 1) * 136 + nl]     = acc[bt][1];
        Cs[bc * 136 + nl + 8]       = acc[bt][2];
        Cs[(bc + 1) * 136 + nl + 8] = acc[bt][3];
    }
    __syncthreads();
    int b = tid >> 3, nl0 = (tid & 7) * 16;
    #pragma unroll
    for (int i = 0; i < 16; i++) {
        int n = n0 + nl0 + i;
        if (n < N) C[(size_t)b * N + n] = Cs[b * 136 + nl0 + i] + bias[n];
    }
}

// ---------------- softmax stats phase 1 ----------------
__global__ void k_stats1() {
    int s = blockIdx.x, b = blockIdx.y, tid = threadIdx.x;
    __shared__ float rm[256], rz[256];
    const float* sg = g_score_g + (size_t)b * VOCAB;
    int beg = s * (VOCAB / NSPL);
    int end = (s == NSPL - 1) ? VOCAB : beg + (VOCAB / NSPL);
    float m = -1e30f, z = 0.f;
    for (int i = beg + tid; i < end; i += 256) {
        float x = sg[i];
        float nm = fmaxf(m, x);
        z = z * expf(m - nm) + expf(x - nm);
        m = nm;
    }
    rm[tid] = m; rz[tid] = z; __syncthreads();
    for (int off = 128; off > 0; off >>= 1) {
        if (tid < off) {
            float m2 = rm[tid + off], z2 = rz[tid + off];
            float nm = fmaxf(rm[tid], m2);
            rz[tid] = rz[tid] * expf(rm[tid] - nm) + z2 * expf(m2 - nm);
            rm[tid] = nm;
        }
        __syncthreads();
    }
    if (tid == 0) { g_pm[b * NSPL + s] = rm[0]; g_pz[b * NSPL + s] = rz[0]; }
}

// ---------------- softmax stats phase 2 ----------------
__global__ void k_stats2() {
    int b = blockIdx.x, tid = threadIdx.x;
    __shared__ float rm[512], rz[512];
    float x = g_score_c[b * SS + tid];
    rm[tid] = x; rz[tid] = 1.f;
    __syncthreads();
    for (int off = 256; off > 0; off >>= 1) {
        if (tid < off) {
            float m2 = rm[tid + off], z2 = rz[tid + off];
            float nm = fmaxf(rm[tid], m2);
            rz[tid] = rz[tid] * expf(rm[tid] - nm) + z2 * expf(m2 - nm);
            rm[tid] = nm;
        }
        __syncthreads();
    }
    if (tid == 0) {
        float m = rm[0], z = rz[0];
        #pragma unroll
        for (int s = 0; s < NSPL; s++) {
            float m2 = g_pm[b * NSPL + s], z2 = g_pz[b * NSPL + s];
            float nm = fmaxf(m, m2);
            z = z * expf(m - nm) + z2 * expf(m2 - nm);
            m = nm;
        }
        g_mx[b] = m; g_invZ[b] = 1.f / z;
    }
}

// ---------------- prob_g write ----------------
__global__ void k_probs(float* __restrict__ out) {
    int b = blockIdx.y;
    int v = blockIdx.x * 512 + threadIdx.x;
    if (v < VOCAB)
        out[(size_t)b * VOCAB + v] =
            expf(g_score_g[(size_t)b * VOCAB + v] - g_mx[b]) * g_invZ[b];
}

// ---------------- scatter + weighted_new fused ----------------
__global__ void k_scatter_weighted(const int* __restrict__ encoded_idx,
                                   const int* __restrict__ input_idx,
                                   const float* __restrict__ encoded,
                                   float* __restrict__ out,
                                   float* __restrict__ outw) {
    int b = blockIdx.x, s = threadIdx.x;
    int t = b * SS + s;
    __shared__ float red[512];
    __shared__ float sws[SS];
    float sc = g_score_c[t];
    float p = expf(sc - g_mx[b]) * g_invZ[b];
    int idx = encoded_idx[t];
    atomicAdd(out + (size_t)b * VOCAB + idx, p);
    float sw = ((idx != 0) && (idx == input_idx[b])) ? sc : 0.f;
    red[s] = sw; __syncthreads();
    for (int off = 256; off > 0; off >>= 1) {
        if (s < off) red[s] += red[s + off];
        __syncthreads();
    }
    float den = red[0];
    float scale = (den > 0.f) ? (1.f / den) : 1.f;
    sws[s] = sw * scale;
    __syncthreads();
    float a0 = 0.f, a1 = 0.f;
    const float* eb = encoded + (size_t)b * SS * TWOH;
    for (int q = 0; q < SS; q++) {
        float w = sws[q];
        if (w == 0.f) continue;
        a0 += w * eb[(size_t)q * TWOH + s];
        a1 += w * eb[(size_t)q * TWOH + s + 512];
    }
    outw[b * TWOH + s] = a0;
    outw[b * TWOH + s + 512] = a1;
}

// ---------------- launcher (two streams, fork/join) ----------------
extern "C" void kernel_launch(void* const* d_in, const int* in_sizes, int n_in,
                              void* d_out, int out_size) {
    const int*   input_idx   = (const int*)d_in[0];
    const float* encoded     = (const float*)d_in[1];
    const int*   encoded_idx = (const int*)d_in[2];
    const float* prev_state  = (const float*)d_in[3];
    const float* weighted    = (const float*)d_in[4];
    int off = (n_in >= 6 && in_sizes[5] <= 4) ? 1 : 0;
    const float* embed_w  = (const float*)d_in[5 + off];
    const float* gru_wih  = (const float*)d_in[6 + off];
    const float* gru_whh  = (const float*)d_in[7 + off];
    const float* gru_bih  = (const float*)d_in[8 + off];
    const float* gru_bhh  = (const float*)d_in[9 + off];
    const float* Wo_w     = (const float*)d_in[10 + off];
    const float* Wo_b     = (const float*)d_in[11 + off];
    const float* Wc_w     = (const float*)d_in[12 + off];
    const float* Wc_b     = (const float*)d_in[13 + off];

    float* out_probs    = (float*)d_out;
    float* out_state    = (float*)d_out + (size_t)BB * VOCAB;
    float* out_weighted = (float*)d_out + (size_t)BB * VOCAB + (size_t)BB * HDIM;

    float *px, *pstate, *psg;
    cudaGetSymbolAddress((void**)&px, g_x);
    cudaGetSymbolAddress((void**)&pstate, g_state);
    cudaGetSymbolAddress((void**)&psg, g_score_g);

    // one-time host-side handles (host objects only; created on first call,
    // which is the uncaptured correctness run)
    static cudaStream_t s2 = nullptr;
    static cudaEvent_t ev_fork = nullptr, ev_state = nullptr, ev_cvt = nullptr, ev_side = nullptr;
    if (s2 == nullptr) {
        cudaStreamCreateWithFlags(&s2, cudaStreamNonBlocking);
        cudaEventCreateWithFlags(&ev_fork, cudaEventDisableTiming);
        cudaEventCreateWithFlags(&ev_state, cudaEventDisableTiming);
        cudaEventCreateWithFlags(&ev_cvt, cudaEventDisableTiming);
        cudaEventCreateWithFlags(&ev_side, cudaEventDisableTiming);
    }

    // fork: side stream converts encoded+Wc_w while main runs GRU chain
    cudaEventRecord(ev_fork, 0);
    cudaStreamWaitEvent(s2, ev_fork, 0);
    {
        long long total = (long long)BB * SS * TWOH / 8 + (long long)HDIM * TWOH / 8;
        k_cvt<<<(int)((total + 255) / 256), 256, 0, s2>>>(encoded, Wc_w);
    }
    cudaEventRecord(ev_cvt, s2);

    k_setup<<<(BB * G3H + 255) / 256, 256>>>(gru_bih, gru_bhh, input_idx, embed_w, weighted);
    k_gigh<<<288, 128>>>(px, prev_state, gru_wih, gru_whh);
    k_gru<<<BB, HDIM>>>(prev_state, out_state);
    cudaEventRecord(ev_state, 0);

    // main: wc (needs cvt + state)
    cudaStreamWaitEvent(0, ev_cvt, 0);
    dim3 wg(HDIM / 128, (BB * SS) / 128);
    k_wc_mma<<<wg, 256>>>(Wc_b);

    // side: wo + stats1 (needs state only) — overlaps with wc
    cudaStreamWaitEvent(s2, ev_state, 0);
    k_wo_tf32<<<(VOCAB + 127) / 128, 256, 0, s2>>>(pstate, Wo_w, Wo_b, psg, VOCAB, HDIM);
    dim3 sg1(NSPL, BB);
    k_stats1<<<sg1, 256, 0, s2>>>();
    cudaEventRecord(ev_side, s2);

    // join: stats2 needs score_c (main) + partials (side)
    cudaStreamWaitEvent(0, ev_side, 0);
    k_stats2<<<BB, 512>>>();
    dim3 pg((VOCAB + 511) / 512, BB);
    k_probs<<<pg, 512>>>(out_probs);
    k_scatter_weighted<<<BB, 512>>>(encoded_idx, input_idx, encoded, out_probs, out_weighted);
}

// round 17
// speedup vs baseline: 1.0422x; 1.0422x over previous
#include <cuda_runtime.h>
#include <cuda_bf16.h>
#include <math.h>

#define VOCAB 50000
#define EDIM  256
#define HDIM  512
#define BB    32
#define SS    512
#define TWOH  1024
#define XDIM  1280   // E + 2H
#define G3H   1536   // 3H
#define WST   20     // smem row stride in 32-bit words (bf16 kernels)
#define PAD   36     // smem row stride in floats (tf32 kernel)
#define NBLK  391    // wo blocks = ceil(VOCAB/128)

// ---------------- device scratch ----------------
__device__ float g_x[BB * XDIM];
__device__ float g_gi[BB * G3H];
__device__ float g_gh[BB * G3H];
__device__ float g_state[BB * HDIM];
__device__ float g_score_g[BB * VOCAB];
__device__ float g_score_c[BB * SS];
__device__ float g_pm2[BB * NBLK];
__device__ float g_pz2[BB * NBLK];
__device__ float g_mx[BB];
__device__ float g_invZ[BB];
__device__ __align__(16) unsigned g_enc_bf16[BB * SS * (TWOH / 2)];  // encoded, packed bf16
__device__ __align__(16) unsigned g_wc_bf16[HDIM * (TWOH / 2)];      // Wc_w, packed bf16

__device__ __forceinline__ void mma_bf16(float* d, const unsigned* a, const unsigned* b) {
    asm volatile(
        "mma.sync.aligned.m16n8k16.row.col.f32.bf16.bf16.f32 "
        "{%0,%1,%2,%3}, {%4,%5,%6,%7}, {%8,%9}, {%0,%1,%2,%3};\n"
        : "+f"(d[0]), "+f"(d[1]), "+f"(d[2]), "+f"(d[3])
        : "r"(a[0]), "r"(a[1]), "r"(a[2]), "r"(a[3]), "r"(b[0]), "r"(b[1]));
}

__device__ __forceinline__ void mma_tf32(float* d, const unsigned* a, const unsigned* b) {
    asm volatile(
        "mma.sync.aligned.m16n8k8.row.col.f32.tf32.tf32.f32 "
        "{%0,%1,%2,%3}, {%4,%5,%6,%7}, {%8,%9}, {%0,%1,%2,%3};\n"
        : "+f"(d[0]), "+f"(d[1]), "+f"(d[2]), "+f"(d[3])
        : "r"(a[0]), "r"(a[1]), "r"(a[2]), "r"(a[3]), "r"(b[0]), "r"(b[1]));
}

__device__ __forceinline__ void ldsm_x4(unsigned& r0, unsigned& r1, unsigned& r2,
                                        unsigned& r3, unsigned addr) {
    asm volatile("ldmatrix.sync.aligned.m8n8.x4.shared.b16 {%0,%1,%2,%3}, [%4];"
        : "=r"(r0), "=r"(r1), "=r"(r2), "=r"(r3) : "r"(addr));
}

__device__ __forceinline__ void cvt_pair(float x0, float x1, unsigned& hi, unsigned& lo) {
    __nv_bfloat162 h = __floats2bfloat162_rn(x0, x1);
    float r0 = x0 - __bfloat162float(h.x);
    float r1 = x1 - __bfloat162float(h.y);
    __nv_bfloat162 l = __floats2bfloat162_rn(r0, r1);
    hi = *(unsigned*)&h;
    lo = *(unsigned*)&l;
}

__device__ __forceinline__ unsigned pack_hi(float x0, float x1) {
    __nv_bfloat162 h = __floats2bfloat162_rn(x0, x1);
    return *(unsigned*)&h;
}

__device__ __forceinline__ float sigf(float x) { return 1.f / (1.f + expf(-x)); }

// ---------------- setup + bf16 pre-convert (one launch) ----------------
__global__ void k_setup(const float* __restrict__ bih, const float* __restrict__ bhh,
                        const int* __restrict__ input_idx,
                        const float* __restrict__ embed_w,
                        const float* __restrict__ weighted,
                        const float* __restrict__ enc,
                        const float* __restrict__ wc) {
    long long t = (long long)blockIdx.x * 256 + threadIdx.x;
    const long long NA = (long long)BB * SS * TWOH / 8;        // 2,097,152 uint4
    const long long NW = (long long)HDIM * TWOH / 8;           // 65,536 uint4
    if (t < NA) {
        const float4* src = (const float4*)enc;
        float4 a = src[2 * t], b = src[2 * t + 1];
        ((uint4*)g_enc_bf16)[t] = make_uint4(pack_hi(a.x, a.y), pack_hi(a.z, a.w),
                                             pack_hi(b.x, b.y), pack_hi(b.z, b.w));
    } else if (t < NA + NW) {
        long long i = t - NA;
        const float4* src = (const float4*)wc;
        float4 a = src[2 * i], b = src[2 * i + 1];
        ((uint4*)g_wc_bf16)[i] = make_uint4(pack_hi(a.x, a.y), pack_hi(a.z, a.w),
                                            pack_hi(b.x, b.y), pack_hi(b.z, b.w));
    }
    if (t < BB * G3H) { int n = (int)(t % G3H); g_gi[t] = bih[n]; g_gh[t] = bhh[n]; }
    if (t < BB * SS) g_score_c[t] = 0.f;
    if (t < BB * XDIM) {
        int b = (int)(t / XDIM), i = (int)(t % XDIM);
        g_x[t] = (i < EDIM) ? embed_w[(size_t)input_idx[b] * EDIM + i]
                            : weighted[b * TWOH + (i - EDIM)];
    }
}

// =====================================================================
// Fused GRU GEMMs: blocks [0,192): gi += x @ wih^T; [192,288): gh += prev @ whh^T
// bf16x2 3-pass (full precision), 128 threads, 64 n-rows/tile, N=G3H both.
// =====================================================================
__global__ __launch_bounds__(128) void k_gigh(
        const float* __restrict__ x, const float* __restrict__ prev,
        const float* __restrict__ wih, const float* __restrict__ whh) {
    __shared__ unsigned Wh[64 * WST], Wl[64 * WST], Xh[32 * WST], Xl[32 * WST];
    int bid = blockIdx.x;
    const float *A, *W; float* C; int K, tile, kbeg;
    if (bid < 192) {
        A = x; W = wih; C = g_gi; K = XDIM;
        tile = bid % 24; kbeg = (bid / 24) * 160;
    } else {
        int l = bid - 192;
        A = prev; W = whh; C = g_gh; K = HDIM;
        tile = l % 24; kbeg = (l / 24) * 128;
    }
    int kend = kbeg + ((bid < 192) ? 160 : 128);
    int n0 = tile * 64;
    int tid = threadIdx.x, warp = tid >> 5, lane = tid & 31;
    int gid = lane >> 2, t = lane & 3;
    float acc[4][4] = {};

    int wrow = tid >> 1;
    int wc0 = (tid & 1) * 16, wcw = (tid & 1) * 8;
    int xrow = tid >> 2, xc0 = (tid & 3) * 8;

    for (int k0 = kbeg; k0 < kend; k0 += 32) {
        #pragma unroll
        for (int i = 0; i < 2; i++) {
            float4 v  = *(const float4*)(W + (size_t)(n0 + wrow) * K + k0 + wc0 + 8 * i);
            float4 v2 = *(const float4*)(W + (size_t)(n0 + wrow) * K + k0 + wc0 + 8 * i + 4);
            unsigned h0, l0, h1, l1, h2, l2, h3, l3;
            cvt_pair(v.x, v.y, h0, l0);  cvt_pair(v.z, v.w, h1, l1);
            cvt_pair(v2.x, v2.y, h2, l2); cvt_pair(v2.z, v2.w, h3, l3);
            Wh[wrow * WST + wcw + 4 * i]     = h0;
            Wh[wrow * WST + wcw + 4 * i + 1] = h1;
            Wh[wrow * WST + wcw + 4 * i + 2] = h2;
            Wh[wrow * WST + wcw + 4 * i + 3] = h3;
            Wl[wrow * WST + wcw + 4 * i]     = l0;
            Wl[wrow * WST + wcw + 4 * i + 1] = l1;
            Wl[wrow * WST + wcw + 4 * i + 2] = l2;
            Wl[wrow * WST + wcw + 4 * i + 3] = l3;
        }
        #pragma unroll
        for (int i = 0; i < 2; i++) {
            float4 v = *(const float4*)(A + (size_t)xrow * K + k0 + xc0 + 4 * i);
            unsigned h0, l0, h1, l1;
            cvt_pair(v.x, v.y, h0, l0); cvt_pair(v.z, v.w, h1, l1);
            Xh[xrow * WST + (xc0 >> 1) + 2 * i]     = h0;
            Xh[xrow * WST + (xc0 >> 1) + 2 * i + 1] = h1;
            Xl[xrow * WST + (xc0 >> 1) + 2 * i]     = l0;
            Xl[xrow * WST + (xc0 >> 1) + 2 * i + 1] = l1;
        }
        __syncthreads();
        #pragma unroll
        for (int s = 0; s < 2; s++) {
            int kb = s * 8;
            int rb = warp * 16;
            unsigned ah[4], al[4];
            ah[0] = Wh[(rb + gid) * WST + kb + t];     ah[1] = Wh[(rb + gid + 8) * WST + kb + t];
            ah[2] = Wh[(rb + gid) * WST + kb + t + 4]; ah[3] = Wh[(rb + gid + 8) * WST + kb + t + 4];
            al[0] = Wl[(rb + gid) * WST + kb + t];     al[1] = Wl[(rb + gid + 8) * WST + kb + t];
            al[2] = Wl[(rb + gid) * WST + kb + t + 4]; al[3] = Wl[(rb + gid + 8) * WST + kb + t + 4];
            #pragma unroll
            for (int bt = 0; bt < 4; bt++) {
                unsigned bh[2], bl[2];
                bh[0] = Xh[(bt * 8 + gid) * WST + kb + t];
                bh[1] = Xh[(bt * 8 + gid) * WST + kb + t + 4];
                bl[0] = Xl[(bt * 8 + gid) * WST + kb + t];
                bl[1] = Xl[(bt * 8 + gid) * WST + kb + t + 4];
                mma_bf16(acc[bt], ah, bh);
                mma_bf16(acc[bt], ah, bl);
                mma_bf16(acc[bt], al, bh);
            }
        }
        __syncthreads();
    }

    int nb = n0 + warp * 16 + gid;
    #pragma unroll
    for (int bt = 0; bt < 4; bt++) {
        int bc = bt * 8 + 2 * t;
        atomicAdd(&C[(size_t)bc * G3H + nb],           acc[bt][0]);
        atomicAdd(&C[(size_t)(bc + 1) * G3H + nb],     acc[bt][1]);
        atomicAdd(&C[(size_t)bc * G3H + nb + 8],       acc[bt][2]);
        atomicAdd(&C[(size_t)(bc + 1) * G3H + nb + 8], acc[bt][3]);
    }
}

// ---------------- GRU cell elementwise ----------------
__global__ void k_gru(const float* __restrict__ prev, float* __restrict__ out_state) {
    int b = blockIdx.x, j = threadIdx.x;
    float gir = g_gi[b * G3H + j];
    float giz = g_gi[b * G3H + HDIM + j];
    float gin = g_gi[b * G3H + 2 * HDIM + j];
    float ghr = g_gh[b * G3H + j];
    float ghz = g_gh[b * G3H + HDIM + j];
    float ghn = g_gh[b * G3H + 2 * HDIM + j];
    float r = sigf(gir + ghr);
    float z = sigf(giz + ghz);
    float n = tanhf(gin + r * ghn);
    float h = prev[b * HDIM + j];
    float st = (1.f - z) * n + z * h;
    g_state[b * HDIM + j] = st;
    out_state[b * HDIM + j] = st;
}

// =====================================================================
// Fused Wc GEMM: bf16 pre-converted; ldmatrix; register-prefetch ping-pong
// (verified R13 version).
// =====================================================================
__global__ __launch_bounds__(256) void k_wc_mma(const float* __restrict__ bias) {
    __shared__ unsigned Ah[2][128 * WST], Bh[2][128 * WST];
    int tid = threadIdx.x;
    int warp = tid >> 5, lane = tid & 31;
    int gid = lane >> 2, t = lane & 3;
    int wm = warp >> 2, wn = warp & 3;
    int m0 = blockIdx.y * 128, n0 = blockIdx.x * 128;

    float acc[4][4][4] = {};

    int srow = tid >> 1;
    int half = tid & 1;
    int scw = half * 8;

    unsigned smem_a[2], smem_b[2];
    smem_a[0] = (unsigned)__cvta_generic_to_shared(Ah[0]);
    smem_a[1] = (unsigned)__cvta_generic_to_shared(Ah[1]);
    smem_b[0] = (unsigned)__cvta_generic_to_shared(Bh[0]);
    smem_b[1] = (unsigned)__cvta_generic_to_shared(Bh[1]);
    int lane15 = lane & 15;
    int asel   = lane >> 4;
    int li     = lane & 7;
    int bsel   = lane >> 3;

    const uint4* pa = (const uint4*)g_enc_bf16 + (size_t)(m0 + srow) * 128 + half * 2;
    const uint4* pw = (const uint4*)g_wc_bf16 + (size_t)(n0 + srow) * 128 + half * 2;

    uint4 va0, va1, vw0, vw1;
    va0 = pa[0]; va1 = pa[1]; vw0 = pw[0]; vw1 = pw[1];
    {
        unsigned* dsta = Ah[0] + srow * WST + scw;
        unsigned* dstb = Bh[0] + srow * WST + scw;
        *(uint4*)dsta = va0; *(uint4*)(dsta + 4) = va1;
        *(uint4*)dstb = vw0; *(uint4*)(dstb + 4) = vw1;
    }
    __syncthreads();

    const int NITER = TWOH / 32;   // 32
    for (int it = 0; it < NITER; it++) {
        int cur = it & 1;
        bool more = (it + 1) < NITER;
        if (more) {
            int o = (it + 1) * 4;
            va0 = pa[o]; va1 = pa[o + 1];
            vw0 = pw[o]; vw1 = pw[o + 1];
        }
        #pragma unroll
        for (int s = 0; s < 2; s++) {
            int kb = s * 8;
            unsigned ah[4][4], bh[4][2];
            #pragma unroll
            for (int mt = 0; mt < 4; mt++) {
                unsigned addr = smem_a[cur] +
                    (((wm * 64 + mt * 16 + lane15) * WST + kb + asel * 4) << 2);
                ldsm_x4(ah[mt][0], ah[mt][1], ah[mt][2], ah[mt][3], addr);
            }
            #pragma unroll
            for (int p = 0; p < 2; p++) {
                int row = wn * 32 + p * 16 + (bsel >> 1) * 8 + li;
                unsigned addr = smem_b[cur] + ((row * WST + kb + (bsel & 1) * 4) << 2);
                ldsm_x4(bh[2 * p][0], bh[2 * p][1], bh[2 * p + 1][0], bh[2 * p + 1][1], addr);
            }
            #pragma unroll
            for (int mt = 0; mt < 4; mt++)
                #pragma unroll
                for (int nt = 0; nt < 4; nt++)
                    mma_bf16(acc[mt][nt], ah[mt], bh[nt]);
        }
        if (more) {
            int nxt = cur ^ 1;
            unsigned* dsta = Ah[nxt] + srow * WST + scw;
            unsigned* dstb = Bh[nxt] + srow * WST + scw;
            *(uint4*)dsta = va0; *(uint4*)(dsta + 4) = va1;
            *(uint4*)dstb = vw0; *(uint4*)(dstb + 4) = vw1;
        }
        __syncthreads();
    }

    int b = m0 >> 9;
    #pragma unroll
    for (int mt = 0; mt < 4; mt++) {
        float r0 = 0.f, r1 = 0.f;
        #pragma unroll
        for (int nt = 0; nt < 4; nt++) {
            int nbase = n0 + wn * 32 + nt * 8 + t * 2;
            #pragma unroll
            for (int j = 0; j < 2; j++) {
                float bs = bias[nbase + j];
                float st = g_state[b * HDIM + nbase + j];
                r0 += sigf(acc[mt][nt][j] + bs) * st;
                r1 += sigf(acc[mt][nt][2 + j] + bs) * st;
            }
        }
        r0 += __shfl_xor_sync(0xffffffffu, r0, 1);
        r0 += __shfl_xor_sync(0xffffffffu, r0, 2);
        r1 += __shfl_xor_sync(0xffffffffu, r1, 1);
        r1 += __shfl_xor_sync(0xffffffffu, r1, 2);
        if (t == 0) {
            int row = m0 + wm * 64 + mt * 16 + gid;
            atomicAdd(&g_score_c[row], r0);
            atomicAdd(&g_score_c[row + 8], r1);
        }
    }
}

// =====================================================================
// Wo GEMM (tf32) + fused softmax partials: C = state @ Wo^T + bias,
// per-(batch, block) online (m, z) partials written to g_pm2/g_pz2.
// =====================================================================
__global__ __launch_bounds__(256) void k_wo_tf32(
        const float* __restrict__ A, const float* __restrict__ W,
        const float* __restrict__ bias, float* __restrict__ C,
        int N, int K) {
    __shared__ float Ws[128 * PAD];
    __shared__ float Xs[32 * PAD];
    __shared__ float Cs[32 * 136];
    int tid = threadIdx.x;
    int warp = tid >> 5, lane = tid & 31;
    int gid = lane >> 2, t = lane & 3;
    int n0 = blockIdx.x * 128;

    float acc[4][4] = {};

    int wrow = tid >> 1, wcol = (tid & 1) * 16;
    int xb = tid >> 3, xk = (tid & 7) * 4;
    bool wok = (n0 + wrow) < N;

    for (int k0 = 0; k0 < K; k0 += 32) {
        #pragma unroll
        for (int i = 0; i < 4; i++) {
            float4 v = make_float4(0.f, 0.f, 0.f, 0.f);
            if (wok) v = *(const float4*)(W + (size_t)(n0 + wrow) * K + k0 + wcol + 4 * i);
            *(float4*)(Ws + wrow * PAD + wcol + 4 * i) = v;
        }
        {
            float4 v = *(const float4*)(A + (size_t)xb * K + k0 + xk);
            *(float4*)(Xs + xb * PAD + xk) = v;
        }
        __syncthreads();
        #pragma unroll
        for (int ks = 0; ks < 32; ks += 8) {
            unsigned a[4];
            int rb = warp * 16;
            a[0] = __float_as_uint(Ws[(rb + gid) * PAD + ks + t]);
            a[1] = __float_as_uint(Ws[(rb + gid + 8) * PAD + ks + t]);
            a[2] = __float_as_uint(Ws[(rb + gid) * PAD + ks + t + 4]);
            a[3] = __float_as_uint(Ws[(rb + gid + 8) * PAD + ks + t + 4]);
            #pragma unroll
            for (int bt = 0; bt < 4; bt++) {
                unsigned bb[2];
                bb[0] = __float_as_uint(Xs[(bt * 8 + gid) * PAD + ks + t]);
                bb[1] = __float_as_uint(Xs[(bt * 8 + gid) * PAD + ks + t + 4]);
                mma_tf32(acc[bt], a, bb);
            }
        }
        __syncthreads();
    }

    #pragma unroll
    for (int bt = 0; bt < 4; bt++) {
        int bc = bt * 8 + t * 2;
        int nl = warp * 16 + gid;
        Cs[bc * 136 + nl]           = acc[bt][0];
        Cs[(bc + 1) * 136 + nl]     = acc[bt][1];
        Cs[bc * 136 + nl + 8]       = acc[bt][2];
        Cs[(bc + 1) * 136 + nl + 8] = acc[bt][3];
    }
    __syncthreads();
    int b = tid >> 3, nl0 = (tid & 7) * 16;
    float m = -1e30f, z = 0.f;
    #pragma unroll
    for (int i = 0; i < 16; i++) {
        int n = n0 + nl0 + i;
        if (n < N) {
            float v = Cs[b * 136 + nl0 + i] + bias[n];
            C[(size_t)b * N + n] = v;
            float nm = fmaxf(m, v);
            z = z * expf(m - nm) + expf(v - nm);
            m = nm;
        }
    }
    // reduce across the 8 threads of this batch row (lane-aligned groups of 8)
    #pragma unroll
    for (int o = 1; o < 8; o <<= 1) {
        float m2 = __shfl_xor_sync(0xffffffffu, m, o);
        float z2 = __shfl_xor_sync(0xffffffffu, z, o);
        float nm = fmaxf(m, m2);
        z = z * expf(m - nm) + z2 * expf(m2 - nm);
        m = nm;
    }
    if ((tid & 7) == 0) {
        g_pm2[b * NBLK + blockIdx.x] = m;
        g_pz2[b * NBLK + blockIdx.x] = z;
    }
}

// ---------------- softmax stats: combine wo partials + score_c ----------------
__global__ void k_stats2() {
    int b = blockIdx.x, tid = threadIdx.x;   // 512 threads
    __shared__ float rm[512], rz[512];
    float m = g_score_c[b * SS + tid];
    float z = 1.f;
    for (int i = tid; i < NBLK; i += 512) {
        float m2 = g_pm2[b * NBLK + i], z2 = g_pz2[b * NBLK + i];
        float nm = fmaxf(m, m2);
        z = z * expf(m - nm) + z2 * expf(m2 - nm);
        m = nm;
    }
    rm[tid] = m; rz[tid] = z;
    __syncthreads();
    for (int off = 256; off > 0; off >>= 1) {
        if (tid < off) {
            float m2 = rm[tid + off], z2 = rz[tid + off];
            float nm = fmaxf(rm[tid], m2);
            rz[tid] = rz[tid] * expf(rm[tid] - nm) + z2 * expf(m2 - nm);
            rm[tid] = nm;
        }
        __syncthreads();
    }
    if (tid == 0) { g_mx[b] = rm[0]; g_invZ[b] = 1.f / rz[0]; }
}

// ---------------- prob_g write ----------------
__global__ void k_probs(float* __restrict__ out) {
    int b = blockIdx.y;
    int v = blockIdx.x * 512 + threadIdx.x;
    if (v < VOCAB)
        out[(size_t)b * VOCAB + v] =
            expf(g_score_g[(size_t)b * VOCAB + v] - g_mx[b]) * g_invZ[b];
}

// ---------------- scatter + weighted_new fused ----------------
__global__ void k_scatter_weighted(const int* __restrict__ encoded_idx,
                                   const int* __restrict__ input_idx,
                                   const float* __restrict__ encoded,
                                   float* __restrict__ out,
                                   float* __restrict__ outw) {
    int b = blockIdx.x, s = threadIdx.x;
    int t = b * SS + s;
    __shared__ float red[512];
    __shared__ float sws[SS];
    float sc = g_score_c[t];
    float p = expf(sc - g_mx[b]) * g_invZ[b];
    int idx = encoded_idx[t];
    atomicAdd(out + (size_t)b * VOCAB + idx, p);
    float sw = ((idx != 0) && (idx == input_idx[b])) ? sc : 0.f;
    red[s] = sw; __syncthreads();
    for (int off = 256; off > 0; off >>= 1) {
        if (s < off) red[s] += red[s + off];
        __syncthreads();
    }
    float den = red[0];
    float scale = (den > 0.f) ? (1.f / den) : 1.f;
    sws[s] = sw * scale;
    __syncthreads();
    float a0 = 0.f, a1 = 0.f;
    const float* eb = encoded + (size_t)b * SS * TWOH;
    for (int q = 0; q < SS; q++) {
        float w = sws[q];
        if (w == 0.f) continue;
        a0 += w * eb[(size_t)q * TWOH + s];
        a1 += w * eb[(size_t)q * TWOH + s + 512];
    }
    outw[b * TWOH + s] = a0;
    outw[b * TWOH + s + 512] = a1;
}

// ---------------- launcher (single stream) ----------------
extern "C" void kernel_launch(void* const* d_in, const int* in_sizes, int n_in,
                              void* d_out, int out_size) {
    const int*   input_idx   = (const int*)d_in[0];
    const float* encoded     = (const float*)d_in[1];
    const int*   encoded_idx = (const int*)d_in[2];
    const float* prev_state  = (const float*)d_in[3];
    const float* weighted    = (const float*)d_in[4];
    int off = (n_in >= 6 && in_sizes[5] <= 4) ? 1 : 0;
    const float* embed_w  = (const float*)d_in[5 + off];
    const float* gru_wih  = (const float*)d_in[6 + off];
    const float* gru_whh  = (const float*)d_in[7 + off];
    const float* gru_bih  = (const float*)d_in[8 + off];
    const float* gru_bhh  = (const float*)d_in[9 + off];
    const float* Wo_w     = (const float*)d_in[10 + off];
    const float* Wo_b     = (const float*)d_in[11 + off];
    const float* Wc_w     = (const float*)d_in[12 + off];
    const float* Wc_b     = (const float*)d_in[13 + off];

    float* out_probs    = (float*)d_out;
    float* out_state    = (float*)d_out + (size_t)BB * VOCAB;
    float* out_weighted = (float*)d_out + (size_t)BB * VOCAB + (size_t)BB * HDIM;

    float *px, *pstate, *psg;
    cudaGetSymbolAddress((void**)&px, g_x);
    cudaGetSymbolAddress((void**)&pstate, g_state);
    cudaGetSymbolAddress((void**)&psg, g_score_g);

    // 1: setup + bf16 convert
    {
        long long total = (long long)BB * SS * TWOH / 8 + (long long)HDIM * TWOH / 8;
        k_setup<<<(int)((total + 255) / 256), 256>>>(gru_bih, gru_bhh, input_idx,
                                                     embed_w, weighted, encoded, Wc_w);
    }
    // 2: gi and gh fused
    k_gigh<<<288, 128>>>(px, prev_state, gru_wih, gru_whh);
    // 3: GRU cell
    k_gru<<<BB, HDIM>>>(prev_state, out_state);
    // 4 (profiled slot): fused sigmoid(enc @ Wc^T + b) . state -> score_c
    dim3 wg(HDIM / 128, (BB * SS) / 128);
    k_wc_mma<<<wg, 256>>>(Wc_b);
    // 5: score_g = state @ Wo^T + bias, with fused softmax partials
    k_wo_tf32<<<NBLK, 256>>>(pstate, Wo_w, Wo_b, psg, VOCAB, HDIM);
    // 6-8: softmax combine + outputs
    k_stats2<<<BB, 512>>>();
    dim3 pg((VOCAB + 511) / 512, BB);
    k_probs<<<pg, 512>>>(out_probs);
    k_scatter_weighted<<<BB, 512>>>(encoded_idx, input_idx, encoded, out_probs, out_weighted);
}